// round 2
// baseline (speedup 1.0000x reference)
#include <cuda_runtime.h>
#include <math.h>

#define D_MODEL 1024
#define D_STATE 64
#define D_CONV  4
#define D_INNER 2048
#define NHEADS  32
#define HEADDIM 64
#define D_PROJ  8224   // 2*D_INNER + NHEADS*(2*D_STATE+1)
#define BATCH   2
#define SEQLEN  1024
#define NTOK    (BATCH*SEQLEN)   // 2048

// Scratch (allocation-free rule: __device__ globals)
__device__ float g_proj [(size_t)NTOK * D_PROJ];   // 67 MB
__device__ float g_xconv[(size_t)NTOK * D_INNER];  // 17 MB
__device__ float g_y    [(size_t)NTOK * D_INNER];  // 17 MB

// ---------------------------------------------------------------------------
// SGEMM "NT": C[m,n] = sum_k A[m*K+k] * B[n*K+k]
// A: M x K row-major, B: N x K row-major, C: M x N row-major.
// Block tile 128x128, K-tile 8, 256 threads, 8x8 per-thread microtile.
// Requires: M % 128 == 0, K % 8 == 0. N may be ragged (guarded).
// ---------------------------------------------------------------------------
__global__ __launch_bounds__(256) void sgemm_nt(
    const float* __restrict__ A, const float* __restrict__ B,
    float* __restrict__ C, int M, int N, int K)
{
    const int tid = threadIdx.x;
    const int bm  = blockIdx.y * 128;
    const int bn  = blockIdx.x * 128;

    __shared__ float As[8][128];
    __shared__ float Bs[8][128];

    const int lrow = tid >> 1;        // 0..127
    const int lk   = (tid & 1) * 4;   // 0 or 4

    const int tx = tid & 15;          // 0..15 -> n microtile
    const int ty = tid >> 4;          // 0..15 -> m microtile

    float acc[8][8];
    #pragma unroll
    for (int i = 0; i < 8; i++)
        #pragma unroll
        for (int j = 0; j < 8; j++)
            acc[i][j] = 0.f;

    const float* Aptr = A + (size_t)(bm + lrow) * K + lk;
    const bool bvalid = (bn + lrow) < N;
    const float* Bptr = B + (size_t)(bvalid ? (bn + lrow) : 0) * K + lk;

    for (int kt = 0; kt < K; kt += 8) {
        float4 av = *reinterpret_cast<const float4*>(Aptr + kt);
        float4 bv = bvalid ? *reinterpret_cast<const float4*>(Bptr + kt)
                           : make_float4(0.f, 0.f, 0.f, 0.f);
        As[lk + 0][lrow] = av.x; As[lk + 1][lrow] = av.y;
        As[lk + 2][lrow] = av.z; As[lk + 3][lrow] = av.w;
        Bs[lk + 0][lrow] = bv.x; Bs[lk + 1][lrow] = bv.y;
        Bs[lk + 2][lrow] = bv.z; Bs[lk + 3][lrow] = bv.w;
        __syncthreads();

        #pragma unroll
        for (int k = 0; k < 8; k++) {
            float4 a0 = *reinterpret_cast<const float4*>(&As[k][ty * 8]);
            float4 a1 = *reinterpret_cast<const float4*>(&As[k][ty * 8 + 4]);
            float4 b0 = *reinterpret_cast<const float4*>(&Bs[k][tx * 8]);
            float4 b1 = *reinterpret_cast<const float4*>(&Bs[k][tx * 8 + 4]);
            float a[8] = {a0.x, a0.y, a0.z, a0.w, a1.x, a1.y, a1.z, a1.w};
            float b[8] = {b0.x, b0.y, b0.z, b0.w, b1.x, b1.y, b1.z, b1.w};
            #pragma unroll
            for (int i = 0; i < 8; i++)
                #pragma unroll
                for (int j = 0; j < 8; j++)
                    acc[i][j] = fmaf(a[i], b[j], acc[i][j]);
        }
        __syncthreads();
    }

    #pragma unroll
    for (int i = 0; i < 8; i++) {
        const int m = bm + ty * 8 + i;
        #pragma unroll
        for (int j = 0; j < 8; j++) {
            const int n = bn + tx * 8 + j;
            if (n < N) C[(size_t)m * N + n] = acc[i][j];
        }
    }
}

// ---------------------------------------------------------------------------
// Depthwise causal conv (width 4) + bias + SiLU on x_inner = proj[:, 0:D_INNER]
// ---------------------------------------------------------------------------
__global__ __launch_bounds__(256) void conv_silu_kernel(
    const float* __restrict__ conv_w, const float* __restrict__ conv_b)
{
    const int idx = blockIdx.x * blockDim.x + threadIdx.x;
    if (idx >= NTOK * D_INNER) return;
    const int c   = idx & (D_INNER - 1);
    const int tok = idx / D_INNER;
    const int b   = tok / SEQLEN;
    const int l   = tok - b * SEQLEN;

    float acc = conv_b[c];
    #pragma unroll
    for (int j = 0; j < D_CONV; j++) {
        const int ll = l - (D_CONV - 1) + j;
        if (ll >= 0)
            acc = fmaf(conv_w[c * D_CONV + j],
                       g_proj[(size_t)(b * SEQLEN + ll) * D_PROJ + c], acc);
    }
    const float sv = acc / (1.f + expf(-acc));   // SiLU
    g_xconv[(size_t)tok * D_INNER + c] = sv;
}

// ---------------------------------------------------------------------------
// Selective scan. One CTA per (head, batch). 64 threads; thread d owns
// head-dim column d with the full 64-entry state in registers.
// Writes final gated output: (y_scan + D*x) * silu(z)  into g_y.
// ---------------------------------------------------------------------------
__global__ __launch_bounds__(64) void scan_kernel(
    const float* __restrict__ A_log, const float* __restrict__ Dp,
    const float* __restrict__ dt_bias)
{
    const int h = blockIdx.x;   // head
    const int b = blockIdx.y;   // batch
    const int d = threadIdx.x;  // 0..63 (head dim AND state index for coop stage)

    __shared__ float4 sABC[D_STATE];  // {dA, dB*dt, C, pad}

    const float Aneg = -expf(A_log[h * D_STATE + d]);  // this thread's s=d
    const float Dh   = Dp[h];
    const float dtb  = dt_bias[h];

    float hreg[D_STATE];
    #pragma unroll
    for (int s = 0; s < D_STATE; s++) hreg[s] = 0.f;

    const int bc_off = 2 * D_INNER + h * (2 * D_STATE + 1);

    for (int l = 0; l < SEQLEN; l++) {
        const int tok = b * SEQLEN + l;
        const float* prow = g_proj + (size_t)tok * D_PROJ;
        const float* bc   = prow + bc_off;

        const float dtraw = bc[2 * D_STATE] + dtb;
        const float dt = (dtraw > 20.f) ? dtraw : log1pf(expf(dtraw));

        const float Bv = bc[d];
        const float Cv = bc[D_STATE + d];
        const float dA = expf(Aneg * dt);
        sABC[d] = make_float4(dA, Bv * dt, Cv, 0.f);
        __syncthreads();

        const float xd = g_xconv[(size_t)tok * D_INNER + h * HEADDIM + d];
        float y0 = 0.f, y1 = 0.f, y2 = 0.f, y3 = 0.f;
        #pragma unroll
        for (int s = 0; s < D_STATE; s += 4) {
            float4 v0 = sABC[s + 0];
            float4 v1 = sABC[s + 1];
            float4 v2 = sABC[s + 2];
            float4 v3 = sABC[s + 3];
            hreg[s + 0] = fmaf(v0.x, hreg[s + 0], v0.y * xd);
            hreg[s + 1] = fmaf(v1.x, hreg[s + 1], v1.y * xd);
            hreg[s + 2] = fmaf(v2.x, hreg[s + 2], v2.y * xd);
            hreg[s + 3] = fmaf(v3.x, hreg[s + 3], v3.y * xd);
            y0 = fmaf(v0.z, hreg[s + 0], y0);
            y1 = fmaf(v1.z, hreg[s + 1], y1);
            y2 = fmaf(v2.z, hreg[s + 2], y2);
            y3 = fmaf(v3.z, hreg[s + 3], y3);
        }
        const float y = (y0 + y1) + (y2 + y3);

        const float z  = prow[D_INNER + h * HEADDIM + d];
        const float sz = z / (1.f + expf(-z));
        g_y[(size_t)tok * D_INNER + h * HEADDIM + d] = fmaf(Dh, xd, y) * sz;
        __syncthreads();  // protect sABC for next step
    }
}

// ---------------------------------------------------------------------------
extern "C" void kernel_launch(void* const* d_in, const int* in_sizes, int n_in,
                              void* d_out, int out_size)
{
    const float* x       = (const float*)d_in[0];  // (2,1024,1024)
    const float* W_in    = (const float*)d_in[1];  // (8224,1024)
    const float* conv_w  = (const float*)d_in[2];  // (2048,1,4)
    const float* conv_b  = (const float*)d_in[3];  // (2048,)
    const float* A_log   = (const float*)d_in[4];  // (32,64)
    const float* Dp      = (const float*)d_in[5];  // (32,)
    const float* dt_bias = (const float*)d_in[6];  // (32,)
    const float* W_out   = (const float*)d_in[7];  // (1024,2048)
    float* out = (float*)d_out;                    // (2,1024,1024)

    float* proj  = nullptr;
    float* xconv = nullptr;  // unused host-side; kernels reference globals
    (void)xconv; (void)in_sizes; (void)n_in; (void)out_size;
    cudaGetSymbolAddress((void**)&proj, g_proj);

    // 1) proj = x @ W_in^T   (M=2048, N=8224, K=1024)
    {
        dim3 grid((D_PROJ + 127) / 128, NTOK / 128);
        sgemm_nt<<<grid, 256>>>(x, W_in, proj, NTOK, D_PROJ, D_MODEL);
    }

    // 2) depthwise conv + SiLU
    {
        const int total = NTOK * D_INNER;
        conv_silu_kernel<<<(total + 255) / 256, 256>>>(conv_w, conv_b);
    }

    // 3) selective scan + gating
    {
        dim3 grid(NHEADS, BATCH);
        scan_kernel<<<grid, 64>>>(A_log, Dp, dt_bias);
    }

    // 4) out = y @ W_out^T   (M=2048, N=1024, K=2048)
    {
        float* yptr = nullptr;
        cudaGetSymbolAddress((void**)&yptr, g_y);
        dim3 grid(D_MODEL / 128, NTOK / 128);
        sgemm_nt<<<grid, 256>>>(yptr, W_out, out, NTOK, D_MODEL, D_INNER);
    }
}

// round 6
// speedup vs baseline: 1.5791x; 1.5791x over previous
#include <cuda_runtime.h>
#include <math.h>

#define D_MODEL 1024
#define D_STATE 64
#define D_CONV  4
#define D_INNER 2048
#define NHEADS  32
#define HEADDIM 64
#define D_PROJ  8224   // 2*D_INNER + NHEADS*(2*D_STATE+1)
#define BATCH   2
#define SEQLEN  1024
#define NTOK    (BATCH*SEQLEN)   // 2048

// Scratch (allocation-free rule: __device__ globals)
__device__ float g_proj [(size_t)NTOK * D_PROJ];   // 67 MB
__device__ float g_xconv[(size_t)NTOK * D_INNER];  // 17 MB
__device__ float g_y    [(size_t)NTOK * D_INNER];  // 17 MB

// ---------------------------------------------------------------------------
// SGEMM "NT": C[m,n] = sum_k A[m*K+k] * B[n*K+k]
// Block tile 128x128, K-tile 8, 256 threads, 8x8 per-thread microtile.
// ---------------------------------------------------------------------------
__global__ __launch_bounds__(256) void sgemm_nt(
    const float* __restrict__ A, const float* __restrict__ B,
    float* __restrict__ C, int M, int N, int K)
{
    const int tid = threadIdx.x;
    const int bm  = blockIdx.y * 128;
    const int bn  = blockIdx.x * 128;

    __shared__ float As[8][128];
    __shared__ float Bs[8][128];

    const int lrow = tid >> 1;        // 0..127
    const int lk   = (tid & 1) * 4;   // 0 or 4

    const int tx = tid & 15;          // 0..15 -> n microtile
    const int ty = tid >> 4;          // 0..15 -> m microtile

    float acc[8][8];
    #pragma unroll
    for (int i = 0; i < 8; i++)
        #pragma unroll
        for (int j = 0; j < 8; j++)
            acc[i][j] = 0.f;

    const float* Aptr = A + (size_t)(bm + lrow) * K + lk;
    const bool bvalid = (bn + lrow) < N;
    const float* Bptr = B + (size_t)(bvalid ? (bn + lrow) : 0) * K + lk;

    for (int kt = 0; kt < K; kt += 8) {
        float4 av = *reinterpret_cast<const float4*>(Aptr + kt);
        float4 bv = bvalid ? *reinterpret_cast<const float4*>(Bptr + kt)
                           : make_float4(0.f, 0.f, 0.f, 0.f);
        As[lk + 0][lrow] = av.x; As[lk + 1][lrow] = av.y;
        As[lk + 2][lrow] = av.z; As[lk + 3][lrow] = av.w;
        Bs[lk + 0][lrow] = bv.x; Bs[lk + 1][lrow] = bv.y;
        Bs[lk + 2][lrow] = bv.z; Bs[lk + 3][lrow] = bv.w;
        __syncthreads();

        #pragma unroll
        for (int k = 0; k < 8; k++) {
            float4 a0 = *reinterpret_cast<const float4*>(&As[k][ty * 8]);
            float4 a1 = *reinterpret_cast<const float4*>(&As[k][ty * 8 + 4]);
            float4 b0 = *reinterpret_cast<const float4*>(&Bs[k][tx * 8]);
            float4 b1 = *reinterpret_cast<const float4*>(&Bs[k][tx * 8 + 4]);
            float a[8] = {a0.x, a0.y, a0.z, a0.w, a1.x, a1.y, a1.z, a1.w};
            float b[8] = {b0.x, b0.y, b0.z, b0.w, b1.x, b1.y, b1.z, b1.w};
            #pragma unroll
            for (int i = 0; i < 8; i++)
                #pragma unroll
                for (int j = 0; j < 8; j++)
                    acc[i][j] = fmaf(a[i], b[j], acc[i][j]);
        }
        __syncthreads();
    }

    #pragma unroll
    for (int i = 0; i < 8; i++) {
        const int m = bm + ty * 8 + i;
        #pragma unroll
        for (int j = 0; j < 8; j++) {
            const int n = bn + tx * 8 + j;
            if (n < N) C[(size_t)m * N + n] = acc[i][j];
        }
    }
}

// ---------------------------------------------------------------------------
// Depthwise causal conv (width 4) + bias + SiLU
// ---------------------------------------------------------------------------
__global__ __launch_bounds__(256) void conv_silu_kernel(
    const float* __restrict__ conv_w, const float* __restrict__ conv_b)
{
    const int idx = blockIdx.x * blockDim.x + threadIdx.x;
    if (idx >= NTOK * D_INNER) return;
    const int c   = idx & (D_INNER - 1);
    const int tok = idx / D_INNER;
    const int b   = tok / SEQLEN;
    const int l   = tok - b * SEQLEN;

    float acc = conv_b[c];
    #pragma unroll
    for (int j = 0; j < D_CONV; j++) {
        const int ll = l - (D_CONV - 1) + j;
        if (ll >= 0)
            acc = fmaf(conv_w[c * D_CONV + j],
                       g_proj[(size_t)(b * SEQLEN + ll) * D_PROJ + c], acc);
    }
    const float sv = acc / (1.f + expf(-acc));   // SiLU
    g_xconv[(size_t)tok * D_INNER + c] = sv;
}

// ---------------------------------------------------------------------------
// Selective scan v2. One CTA per (head, batch), 128 threads.
// Thread (d, sq): d = tid>>1 in [0,64), sq = tid&1. Owns states
// s in [32*sq, 32*sq+32) for head-dim column d (32 state registers).
// All per-step global data is prefetched one step ahead so memory latency
// hides under the previous step's compute.
// Staging: tid<64 computes {dA[s], B[s]*dt}; tid>=64 stages C[s].
// y is reduced across the two state-halves with one shfl_xor(1).
// ---------------------------------------------------------------------------
__global__ __launch_bounds__(128) void scan_kernel(
    const float* __restrict__ A_log, const float* __restrict__ Dp,
    const float* __restrict__ dt_bias)
{
    const int h   = blockIdx.x;   // head
    const int b   = blockIdx.y;   // batch
    const int tid = threadIdx.x;
    const int d   = tid >> 1;     // 0..63
    const int sq  = tid & 1;      // 0..1
    const int s0  = sq * 32;

    __shared__ float4 sABC[D_STATE];  // {dA, dB*dt, C, pad}

    float Aneg = 0.f;
    if (tid < D_STATE) Aneg = -expf(A_log[h * D_STATE + tid]);
    const float Dh  = Dp[h];
    const float dtb = dt_bias[h];

    float hreg[32];
    #pragma unroll
    for (int s = 0; s < 32; s++) hreg[s] = 0.f;

    const int bc_off = 2 * D_INNER + h * (2 * D_STATE + 1);
    const int xz_off = h * HEADDIM + d;

    // ---- prefetch step 0 ----
    int tok = b * SEQLEN;
    {
        const float* prow = g_proj + (size_t)tok * D_PROJ;
        // pBC: B[s] for tid<64, C[s] for tid>=64 -> one coalesced 128-lane load
    }
    const float* prow0 = g_proj + (size_t)tok * D_PROJ;
    float pBC = prow0[bc_off + tid];
    float pdt = prow0[bc_off + 2 * D_STATE];
    float px  = g_xconv[(size_t)tok * D_INNER + xz_off];
    float pz  = prow0[D_INNER + xz_off];

    for (int l = 0; l < SEQLEN; l++) {
        // ---- stage into shared from prefetched registers ----
        const float dtraw = pdt + dtb;
        const float dt = (dtraw > 20.f) ? dtraw : log1pf(expf(dtraw));
        if (tid < D_STATE) {
            sABC[tid].x = expf(Aneg * dt);
            sABC[tid].y = pBC * dt;
        } else {
            sABC[tid - D_STATE].z = pBC;
        }
        const float xd = px;
        const float zv = pz;

        // ---- issue prefetch for step l+1 (independent of recurrence) ----
        {
            const int ln   = (l + 1 < SEQLEN) ? (l + 1) : (SEQLEN - 1);
            const int tokn = b * SEQLEN + ln;
            const float* prown = g_proj + (size_t)tokn * D_PROJ;
            pBC = prown[bc_off + tid];
            pdt = prown[bc_off + 2 * D_STATE];
            px  = g_xconv[(size_t)tokn * D_INNER + xz_off];
            pz  = prown[D_INNER + xz_off];
        }

        __syncthreads();   // staging visible

        // ---- consume: 32 state updates + y partial sums ----
        float y0 = 0.f, y1 = 0.f, y2 = 0.f, y3 = 0.f;
        #pragma unroll
        for (int i = 0; i < 32; i += 4) {
            float4 v0 = sABC[s0 + i + 0];
            float4 v1 = sABC[s0 + i + 1];
            float4 v2 = sABC[s0 + i + 2];
            float4 v3 = sABC[s0 + i + 3];
            hreg[i + 0] = fmaf(v0.x, hreg[i + 0], v0.y * xd);
            hreg[i + 1] = fmaf(v1.x, hreg[i + 1], v1.y * xd);
            hreg[i + 2] = fmaf(v2.x, hreg[i + 2], v2.y * xd);
            hreg[i + 3] = fmaf(v3.x, hreg[i + 3], v3.y * xd);
            y0 = fmaf(v0.z, hreg[i + 0], y0);
            y1 = fmaf(v1.z, hreg[i + 1], y1);
            y2 = fmaf(v2.z, hreg[i + 2], y2);
            y3 = fmaf(v3.z, hreg[i + 3], y3);
        }
        float y = (y0 + y1) + (y2 + y3);
        y += __shfl_xor_sync(0xffffffffu, y, 1);   // partner lane has same d

        if (sq == 0) {
            const float sz = zv / (1.f + expf(-zv));
            g_y[(size_t)tok * D_INNER + xz_off] = fmaf(Dh, xd, y) * sz;
        }
        tok++;
        __syncthreads();   // protect sABC before next staging
    }
}

// ---------------------------------------------------------------------------
extern "C" void kernel_launch(void* const* d_in, const int* in_sizes, int n_in,
                              void* d_out, int out_size)
{
    const float* x       = (const float*)d_in[0];  // (2,1024,1024)
    const float* W_in    = (const float*)d_in[1];  // (8224,1024)
    const float* conv_w  = (const float*)d_in[2];  // (2048,1,4)
    const float* conv_b  = (const float*)d_in[3];  // (2048,)
    const float* A_log   = (const float*)d_in[4];  // (32,64)
    const float* Dp      = (const float*)d_in[5];  // (32,)
    const float* dt_bias = (const float*)d_in[6];  // (32,)
    const float* W_out   = (const float*)d_in[7];  // (1024,2048)
    float* out = (float*)d_out;                    // (2,1024,1024)

    (void)in_sizes; (void)n_in; (void)out_size;

    float* proj = nullptr;
    cudaGetSymbolAddress((void**)&proj, g_proj);

    // 1) proj = x @ W_in^T   (M=2048, N=8224, K=1024)
    {
        dim3 grid((D_PROJ + 127) / 128, NTOK / 128);
        sgemm_nt<<<grid, 256>>>(x, W_in, proj, NTOK, D_PROJ, D_MODEL);
    }

    // 2) depthwise conv + SiLU
    {
        const int total = NTOK * D_INNER;
        conv_silu_kernel<<<(total + 255) / 256, 256>>>(conv_w, conv_b);
    }

    // 3) selective scan + gating
    {
        dim3 grid(NHEADS, BATCH);
        scan_kernel<<<grid, 128>>>(A_log, Dp, dt_bias);
    }

    // 4) out = y @ W_out^T   (M=2048, N=1024, K=2048)
    {
        float* yptr = nullptr;
        cudaGetSymbolAddress((void**)&yptr, g_y);
        dim3 grid(D_MODEL / 128, NTOK / 128);
        sgemm_nt<<<grid, 256>>>(yptr, W_out, out, NTOK, D_MODEL, D_INNER);
    }
}